// round 1
// baseline (speedup 1.0000x reference)
#include <cuda_runtime.h>
#include <cstdint>
#include <math.h>

// ============================================================================
// Problem constants (shapes are fixed by the reference)
// ============================================================================
#define NN     50000
#define EE     1600000
#define DD     128          // feature dim -> 32 float4 per row
#define NITER  20
#define NNEG   10
#define SPAN   49998u       // maxval - minval = 50000 - 2
#define MULT   39100u       // 2^32 % SPAN
#define BIGDEG 5000.0f

// JAX threefry mode: 1 = threefry_partitionable (default in modern JAX),
// 0 = original counter layout. Flip if rel_err is O(1).
#define PARTITIONABLE 1

// ============================================================================
// Scratch (static device globals; no allocation allowed)
// ============================================================================
__device__ float g_repA[NN * DD];
__device__ float g_repB[NN * DD];
__device__ float g_mean[NN * DD];
__device__ float g_grad[NN * DD];
__device__ float g_deg[NN];
__device__ int   g_cnt[NN];
__device__ int   g_rowptr[NN + 1];
__device__ int   g_fill[NN];
__device__ int   g_esrc[EE];
__device__ float g_norm[NITER];

// ============================================================================
// Threefry-2x32 (20 rounds), matches jax._src.prng.threefry2x32
// ============================================================================
__host__ __device__ __forceinline__ void tf2x32(uint32_t k0, uint32_t k1,
                                                uint32_t x0, uint32_t x1,
                                                uint32_t& o0, uint32_t& o1) {
    uint32_t ks2 = k0 ^ k1 ^ 0x1BD11BDAu;
    x0 += k0; x1 += k1;
#define TF_R(r) { x0 += x1; x1 = (x1 << (r)) | (x1 >> (32 - (r))); x1 ^= x0; }
    TF_R(13) TF_R(15) TF_R(26) TF_R(6)   x0 += k1;  x1 += ks2 + 1u;
    TF_R(17) TF_R(29) TF_R(16) TF_R(24)  x0 += ks2; x1 += k0  + 2u;
    TF_R(13) TF_R(15) TF_R(26) TF_R(6)   x0 += k0;  x1 += k1  + 3u;
    TF_R(17) TF_R(29) TF_R(16) TF_R(24)  x0 += k1;  x1 += ks2 + 4u;
    TF_R(13) TF_R(15) TF_R(26) TF_R(6)   x0 += ks2; x1 += k0  + 5u;
#undef TF_R
    o0 = x0; o1 = x1;
}

// random_bits(key, 32, (NN, NNEG)) at flat element index e
__device__ __forceinline__ uint32_t rbits32(uint32_t kx, uint32_t ky, uint32_t e) {
#if PARTITIONABLE
    uint32_t a, b;
    tf2x32(kx, ky, 0u, e, a, b);
    return a ^ b;
#else
    const uint32_t HALF = (NN * NNEG) / 2;  // 250000, size is even
    uint32_t a, b;
    if (e < HALF) { tf2x32(kx, ky, e, e + HALF, a, b); return a; }
    tf2x32(kx, ky, e - HALF, e, a, b); return b;
#endif
}

// ============================================================================
// Build kernels (run once per launch)
// ============================================================================
__global__ void k_zero() {
    int i = blockIdx.x * blockDim.x + threadIdx.x;
    if (i < NN)    g_cnt[i] = 0;
    if (i < NITER) g_norm[i] = 0.0f;
}

__global__ void k_hist(const int* __restrict__ dst) {
    int i = blockIdx.x * blockDim.x + threadIdx.x;
    if (i < EE) atomicAdd(&g_cnt[dst[i]], 1);
}

// Single-block scan: 1024 threads, each owns a contiguous chunk.
__global__ void k_scan() {
    __shared__ int sh[1024];
    const int t = threadIdx.x;
    const int CH = (NN + 1023) / 1024;  // 49
    const int base = t * CH;
    int s = 0;
    for (int j = 0; j < CH; j++) {
        int idx = base + j;
        if (idx < NN) s += g_cnt[idx];
    }
    sh[t] = s;
    __syncthreads();
    for (int off = 1; off < 1024; off <<= 1) {
        int v = (t >= off) ? sh[t - off] : 0;
        __syncthreads();
        sh[t] += v;
        __syncthreads();
    }
    int run = (t == 0) ? 0 : sh[t - 1];
    for (int j = 0; j < CH; j++) {
        int idx = base + j;
        if (idx < NN) {
            int c = g_cnt[idx];
            g_rowptr[idx] = run;
            g_fill[idx]   = run;
            g_deg[idx]    = (float)c;
            run += c;
        }
    }
    if (t == 1023) g_rowptr[NN] = run;  // == EE
}

__global__ void k_scatter(const int* __restrict__ src, const int* __restrict__ dst) {
    int i = blockIdx.x * blockDim.x + threadIdx.x;
    if (i < EE) {
        int p = atomicAdd(&g_fill[dst[i]], 1);
        g_esrc[p] = src[i];
    }
}

__global__ void k_copy(const float4* __restrict__ in) {
    int i = blockIdx.x * blockDim.x + threadIdx.x;
    if (i < NN * (DD / 4)) reinterpret_cast<float4*>(g_repA)[i] = in[i];
}

// ============================================================================
// Iteration kernel 1: mailbox mean (one warp per node, CSR segmented sum)
// ============================================================================
__global__ void k_mean(const float* __restrict__ rep_) {
    const float4* rep = reinterpret_cast<const float4*>(rep_);
    const int w    = (blockIdx.x * blockDim.x + threadIdx.x) >> 5;
    const int lane = threadIdx.x & 31;
    if (w >= NN) return;
    const int s = g_rowptr[w], e = g_rowptr[w + 1];
    float4 acc = make_float4(0.f, 0.f, 0.f, 0.f);
    int i = s;
    for (; i + 4 <= e; i += 4) {
        int s0 = g_esrc[i], s1 = g_esrc[i + 1], s2 = g_esrc[i + 2], s3 = g_esrc[i + 3];
        float4 a = rep[s0 * 32 + lane];
        float4 b = rep[s1 * 32 + lane];
        float4 c = rep[s2 * 32 + lane];
        float4 d = rep[s3 * 32 + lane];
        acc.x += (a.x + b.x) + (c.x + d.x);
        acc.y += (a.y + b.y) + (c.y + d.y);
        acc.z += (a.z + b.z) + (c.z + d.z);
        acc.w += (a.w + b.w) + (c.w + d.w);
    }
    for (; i < e; ++i) {
        float4 a = rep[g_esrc[i] * 32 + lane];
        acc.x += a.x; acc.y += a.y; acc.z += a.z; acc.w += a.w;
    }
    float dinv = 1.0f / fmaxf(g_deg[w], 1.0f);
    reinterpret_cast<float4*>(g_mean)[w * 32 + lane] =
        make_float4(acc.x * dinv, acc.y * dinv, acc.z * dinv, acc.w * dinv);
}

// ============================================================================
// Iteration kernel 2: negatives + softmax grad + global norm accumulation
// ============================================================================
__device__ __forceinline__ float warp_sum(float v) {
#pragma unroll
    for (int o = 16; o > 0; o >>= 1) v += __shfl_xor_sync(0xffffffffu, v, o);
    return v;
}

__global__ void k_grad(const float* __restrict__ rep_, int t,
                       uint32_t k1x, uint32_t k1y, uint32_t k2x, uint32_t k2y) {
    const float4* rep = reinterpret_cast<const float4*>(rep_);
    const int w    = (blockIdx.x * blockDim.x + threadIdx.x) >> 5;
    const int lane = threadIdx.x & 31;
    if (w >= NN) return;

    float4 r = rep[w * 32 + lane];
    float4 m = reinterpret_cast<const float4*>(g_mean)[w * 32 + lane];

    float d0 = warp_sum(r.x * m.x + r.y * m.y + r.z * m.z + r.w * m.w);

    // lanes 0..9 each derive one negative index (exact JAX randint)
    int idx = 0;
    if (lane < NNEG) {
        uint32_t e  = (uint32_t)w * NNEG + (uint32_t)lane;
        uint32_t hi = rbits32(k1x, k1y, e);
        uint32_t lo = rbits32(k2x, k2y, e);
        uint32_t off = ((hi % SPAN) * MULT + (lo % SPAN)) % SPAN;
        idx = 2 + (int)off;
    }

    float4 v[NNEG];
    float  p[NNEG];
#pragma unroll
    for (int j = 0; j < NNEG; j++) {
        int ij = __shfl_sync(0xffffffffu, idx, j);
        v[j] = rep[ij * 32 + lane];
        p[j] = warp_sum(r.x * v[j].x + r.y * v[j].y + r.z * v[j].z + r.w * v[j].w);
    }

    float mx = d0;
#pragma unroll
    for (int j = 0; j < NNEG; j++) mx = fmaxf(mx, p[j]);
    float e0 = expf(d0 - mx);
    float Z  = e0;
#pragma unroll
    for (int j = 0; j < NNEG; j++) { p[j] = expf(p[j] - mx); Z += p[j]; }
    float inv = 1.0f / Z;
    float p0  = e0 * inv;

    float4 g = make_float4((p0 - 1.0f) * m.x, (p0 - 1.0f) * m.y,
                           (p0 - 1.0f) * m.z, (p0 - 1.0f) * m.w);
#pragma unroll
    for (int j = 0; j < NNEG; j++) {
        float pj = p[j] * inv;
        g.x += pj * v[j].x; g.y += pj * v[j].y; g.z += pj * v[j].z; g.w += pj * v[j].w;
    }

    float dg = g_deg[w];
    bool eligible = (dg >= 2.0f) && (dg <= BIGDEG);
    if (!eligible) g = make_float4(0.f, 0.f, 0.f, 0.f);

    reinterpret_cast<float4*>(g_grad)[w * 32 + lane] = g;

    float ss = warp_sum(g.x * g.x + g.y * g.y + g.z * g.z + g.w * g.w);
    if (lane == 0 && ss != 0.0f) atomicAdd(&g_norm[t], ss);
}

// ============================================================================
// Iteration kernel 3: clipped SGD update (+ big-degree mean-pool branch)
// ============================================================================
__global__ void k_update(const float* __restrict__ rep_, float* __restrict__ out_, int t) {
    const int i = blockIdx.x * blockDim.x + threadIdx.x;  // over NN*32 float4s
    if (i >= NN * (DD / 4)) return;
    float S = g_norm[t];
    float coef = fminf(1.0f, 2.0f / (sqrtf(S) + 1e-6f));
    int node = i >> 5;
    float4 res;
    if (g_deg[node] > BIGDEG) {
        res = reinterpret_cast<const float4*>(g_mean)[i];
    } else {
        float4 r = reinterpret_cast<const float4*>(rep_)[i];
        float4 g = reinterpret_cast<const float4*>(g_grad)[i];
        res = make_float4(r.x - coef * g.x, r.y - coef * g.y,
                          r.z - coef * g.z, r.w - coef * g.w);
    }
    reinterpret_cast<float4*>(out_)[i] = res;
}

// ============================================================================
// Host: JAX key derivation (split(key(1),20) -> per-iter randint subkeys)
// ============================================================================
static void derive_keys(uint32_t* k1x, uint32_t* k1y, uint32_t* k2x, uint32_t* k2y) {
    uint32_t kt0[NITER], kt1[NITER];
#if PARTITIONABLE
    for (int t = 0; t < NITER; t++)
        tf2x32(0u, 1u, 0u, (uint32_t)t, kt0[t], kt1[t]);
    for (int t = 0; t < NITER; t++) {
        tf2x32(kt0[t], kt1[t], 0u, 0u, k1x[t], k1y[t]);
        tf2x32(kt0[t], kt1[t], 0u, 1u, k2x[t], k2y[t]);
    }
#else
    // original split: threefry(key, iota(2*num)) reshaped (num, 2)
    uint32_t c[2 * NITER];
    for (int i = 0; i < NITER; i++) {
        uint32_t a, b;
        tf2x32(0u, 1u, (uint32_t)i, (uint32_t)(i + NITER), a, b);
        c[i] = a; c[NITER + i] = b;
    }
    for (int t = 0; t < NITER; t++) { kt0[t] = c[2 * t]; kt1[t] = c[2 * t + 1]; }
    for (int t = 0; t < NITER; t++) {
        // split(key, 2): counts iota(4) -> pairs (0,2),(1,3)
        uint32_t a0, b0, a1, b1;
        tf2x32(kt0[t], kt1[t], 0u, 2u, a0, b0);
        tf2x32(kt0[t], kt1[t], 1u, 3u, a1, b1);
        k1x[t] = a0; k1y[t] = a1;   // row 0 of reshape = (out0[0], out0[1])
        k2x[t] = b0; k2y[t] = b1;   // row 1 = (out1[0], out1[1])
    }
#endif
}

// ============================================================================
// Entry point
// ============================================================================
extern "C" void kernel_launch(void* const* d_in, const int* in_sizes, int n_in,
                              void* d_out, int out_size) {
    const float* repre = (const float*)d_in[0];
    const int*   src   = (const int*)d_in[1];
    const int*   dst   = (const int*)d_in[2];
    float*       out   = (float*)d_out;

    float *repA, *repB;
    cudaGetSymbolAddress((void**)&repA, g_repA);
    cudaGetSymbolAddress((void**)&repB, g_repB);

    uint32_t k1x[NITER], k1y[NITER], k2x[NITER], k2y[NITER];
    derive_keys(k1x, k1y, k2x, k2y);

    const int TB = 256;
    // ---- build phase (once per launch, amortized over 20 iterations) ----
    k_zero<<<(NN + TB - 1) / TB, TB>>>();
    k_hist<<<(EE + TB - 1) / TB, TB>>>(dst);
    k_scan<<<1, 1024>>>();
    k_scatter<<<(EE + TB - 1) / TB, TB>>>(src, dst);
    k_copy<<<(NN * (DD / 4) + TB - 1) / TB, TB>>>((const float4*)repre);

    // ---- 20 iterations, ping-pong buffers, final iter writes d_out ----
    float* cur = repA;
    for (int t = 0; t < NITER; t++) {
        k_mean<<<(NN * 32 + TB - 1) / TB, TB>>>(cur);
        k_grad<<<(NN * 32 + TB - 1) / TB, TB>>>(cur, t, k1x[t], k1y[t], k2x[t], k2y[t]);
        float* nxt = (t == NITER - 1) ? out : ((cur == repA) ? repB : repA);
        k_update<<<(NN * (DD / 4) + TB - 1) / TB, TB>>>(cur, nxt, t);
        cur = nxt;
    }
}

// round 2
// speedup vs baseline: 1.3556x; 1.3556x over previous
#include <cuda_runtime.h>
#include <cstdint>
#include <math.h>

// ============================================================================
// Problem constants (shapes are fixed by the reference)
// ============================================================================
#define NN     50000
#define EE     1600000
#define DD     128          // feature dim -> 32 float4 per row
#define NITER  20
#define NNEG   10
#define SPAN   49998u       // maxval - minval = 50000 - 2
#define MULT   39100u       // 2^32 % SPAN
#define BIGDEG 5000.0f

// ============================================================================
// Scratch (static device globals; no allocation allowed)
// ============================================================================
__device__ float g_repA[NN * DD];
__device__ float g_repB[NN * DD];
__device__ float g_mean[NN * DD];
__device__ float g_grad[NN * DD];
__device__ float g_deg[NN];
__device__ int   g_cnt[NN];
__device__ int   g_rowptr[NN + 1];
__device__ int   g_fill[NN];
__device__ int   g_esrc[EE];
__device__ float g_norm[NITER];

// ============================================================================
// Threefry-2x32 (20 rounds), matches jax._src.prng.threefry2x32
// (threefry_partitionable mode — verified exact in round 1, rel_err 3e-8)
// ============================================================================
__host__ __device__ __forceinline__ void tf2x32(uint32_t k0, uint32_t k1,
                                                uint32_t x0, uint32_t x1,
                                                uint32_t& o0, uint32_t& o1) {
    uint32_t ks2 = k0 ^ k1 ^ 0x1BD11BDAu;
    x0 += k0; x1 += k1;
#define TF_R(r) { x0 += x1; x1 = (x1 << (r)) | (x1 >> (32 - (r))); x1 ^= x0; }
    TF_R(13) TF_R(15) TF_R(26) TF_R(6)   x0 += k1;  x1 += ks2 + 1u;
    TF_R(17) TF_R(29) TF_R(16) TF_R(24)  x0 += ks2; x1 += k0  + 2u;
    TF_R(13) TF_R(15) TF_R(26) TF_R(6)   x0 += k0;  x1 += k1  + 3u;
    TF_R(17) TF_R(29) TF_R(16) TF_R(24)  x0 += k1;  x1 += ks2 + 4u;
    TF_R(13) TF_R(15) TF_R(26) TF_R(6)   x0 += ks2; x1 += k0  + 5u;
#undef TF_R
    o0 = x0; o1 = x1;
}

__device__ __forceinline__ uint32_t rbits32(uint32_t kx, uint32_t ky, uint32_t e) {
    uint32_t a, b;
    tf2x32(kx, ky, 0u, e, a, b);
    return a ^ b;
}

// ============================================================================
// Build kernels (run once per launch)
// ============================================================================
__global__ void k_zero() {
    int i = blockIdx.x * blockDim.x + threadIdx.x;
    if (i < NN)    g_cnt[i] = 0;
    if (i < NITER) g_norm[i] = 0.0f;
}

__global__ void k_hist(const int* __restrict__ dst) {
    int i = blockIdx.x * blockDim.x + threadIdx.x;
    if (i < EE) atomicAdd(&g_cnt[dst[i]], 1);
}

// Single-block scan: 1024 threads, each owns a contiguous chunk.
__global__ void k_scan() {
    __shared__ int sh[1024];
    const int t = threadIdx.x;
    const int CH = (NN + 1023) / 1024;  // 49
    const int base = t * CH;
    int s = 0;
    for (int j = 0; j < CH; j++) {
        int idx = base + j;
        if (idx < NN) s += g_cnt[idx];
    }
    sh[t] = s;
    __syncthreads();
    for (int off = 1; off < 1024; off <<= 1) {
        int v = (t >= off) ? sh[t - off] : 0;
        __syncthreads();
        sh[t] += v;
        __syncthreads();
    }
    int run = (t == 0) ? 0 : sh[t - 1];
    for (int j = 0; j < CH; j++) {
        int idx = base + j;
        if (idx < NN) {
            int c = g_cnt[idx];
            g_rowptr[idx] = run;
            g_fill[idx]   = run;
            g_deg[idx]    = (float)c;
            run += c;
        }
    }
    if (t == 1023) g_rowptr[NN] = run;  // == EE
}

__global__ void k_scatter(const int* __restrict__ src, const int* __restrict__ dst) {
    int i = blockIdx.x * blockDim.x + threadIdx.x;
    if (i < EE) {
        int p = atomicAdd(&g_fill[dst[i]], 1);
        g_esrc[p] = src[i];
    }
}

__global__ void k_copy(const float4* __restrict__ in) {
    int i = blockIdx.x * blockDim.x + threadIdx.x;
    if (i < NN * (DD / 4)) reinterpret_cast<float4*>(g_repA)[i] = in[i];
}

// ============================================================================
// Fused iteration kernel: mailbox mean + negatives + softmax grad + norm.
// One warp per node. Block = 256 threads = 8 nodes. Exactly 6250 blocks.
// ============================================================================
__device__ __forceinline__ float warp_sum(float v) {
#pragma unroll
    for (int o = 16; o > 0; o >>= 1) v += __shfl_xor_sync(0xffffffffu, v, o);
    return v;
}

__global__ void __launch_bounds__(256, 2)
k_meangrad(const float* __restrict__ rep_, int t,
           uint32_t k1x, uint32_t k1y, uint32_t k2x, uint32_t k2y) {
    const float4* rep = reinterpret_cast<const float4*>(rep_);
    const int warp = threadIdx.x >> 5;          // 0..7
    const int w    = blockIdx.x * 8 + warp;     // node id (exact fit: 6250*8=50000)
    const int lane = threadIdx.x & 31;
    __shared__ float sh_ss[8];

    // ---- mailbox mean (CSR segmented sum, unroll 8 for MLP) ----
    const int s = g_rowptr[w], e = g_rowptr[w + 1];
    float4 acc = make_float4(0.f, 0.f, 0.f, 0.f);
    int i = s;
    for (; i + 8 <= e; i += 8) {
        int s0 = g_esrc[i],     s1 = g_esrc[i + 1], s2 = g_esrc[i + 2], s3 = g_esrc[i + 3];
        int s4 = g_esrc[i + 4], s5 = g_esrc[i + 5], s6 = g_esrc[i + 6], s7 = g_esrc[i + 7];
        float4 a = rep[s0 * 32 + lane];
        float4 b = rep[s1 * 32 + lane];
        float4 c = rep[s2 * 32 + lane];
        float4 d = rep[s3 * 32 + lane];
        float4 a2 = rep[s4 * 32 + lane];
        float4 b2 = rep[s5 * 32 + lane];
        float4 c2 = rep[s6 * 32 + lane];
        float4 d2 = rep[s7 * 32 + lane];
        acc.x += ((a.x + b.x) + (c.x + d.x)) + ((a2.x + b2.x) + (c2.x + d2.x));
        acc.y += ((a.y + b.y) + (c.y + d.y)) + ((a2.y + b2.y) + (c2.y + d2.y));
        acc.z += ((a.z + b.z) + (c.z + d.z)) + ((a2.z + b2.z) + (c2.z + d2.z));
        acc.w += ((a.w + b.w) + (c.w + d.w)) + ((a2.w + b2.w) + (c2.w + d2.w));
    }
    for (; i < e; ++i) {
        float4 a = rep[g_esrc[i] * 32 + lane];
        acc.x += a.x; acc.y += a.y; acc.z += a.z; acc.w += a.w;
    }
    const float dg   = g_deg[w];
    const float dinv = 1.0f / fmaxf(dg, 1.0f);
    float4 m = make_float4(acc.x * dinv, acc.y * dinv, acc.z * dinv, acc.w * dinv);
    reinterpret_cast<float4*>(g_mean)[w * 32 + lane] = m;

    // ---- contrastive grad ----
    float4 r = rep[w * 32 + lane];
    float d0 = warp_sum(r.x * m.x + r.y * m.y + r.z * m.z + r.w * m.w);

    // lanes 0..9 each derive one negative index (exact JAX randint)
    int idx = 0;
    if (lane < NNEG) {
        uint32_t el = (uint32_t)w * NNEG + (uint32_t)lane;
        uint32_t hi = rbits32(k1x, k1y, el);
        uint32_t lo = rbits32(k2x, k2y, el);
        uint32_t off = ((hi % SPAN) * MULT + (lo % SPAN)) % SPAN;
        idx = 2 + (int)off;
    }

    float4 v[NNEG];
    float  p[NNEG];
#pragma unroll
    for (int j = 0; j < NNEG; j++) {
        int ij = __shfl_sync(0xffffffffu, idx, j);
        v[j] = rep[ij * 32 + lane];
        p[j] = warp_sum(r.x * v[j].x + r.y * v[j].y + r.z * v[j].z + r.w * v[j].w);
    }

    float mx = d0;
#pragma unroll
    for (int j = 0; j < NNEG; j++) mx = fmaxf(mx, p[j]);
    float e0 = expf(d0 - mx);
    float Z  = e0;
#pragma unroll
    for (int j = 0; j < NNEG; j++) { p[j] = expf(p[j] - mx); Z += p[j]; }
    float inv = 1.0f / Z;
    float p0  = e0 * inv;

    float4 g = make_float4((p0 - 1.0f) * m.x, (p0 - 1.0f) * m.y,
                           (p0 - 1.0f) * m.z, (p0 - 1.0f) * m.w);
#pragma unroll
    for (int j = 0; j < NNEG; j++) {
        float pj = p[j] * inv;
        g.x += pj * v[j].x; g.y += pj * v[j].y; g.z += pj * v[j].z; g.w += pj * v[j].w;
    }

    bool eligible = (dg >= 2.0f) && (dg <= BIGDEG);
    if (!eligible) g = make_float4(0.f, 0.f, 0.f, 0.f);

    reinterpret_cast<float4*>(g_grad)[w * 32 + lane] = g;

    // ---- grad-norm: warp reduce -> smem -> ONE atomic per block ----
    float ss = warp_sum(g.x * g.x + g.y * g.y + g.z * g.z + g.w * g.w);
    if (lane == 0) sh_ss[warp] = ss;
    __syncthreads();
    if (threadIdx.x == 0) {
        float bs = sh_ss[0] + sh_ss[1] + sh_ss[2] + sh_ss[3]
                 + sh_ss[4] + sh_ss[5] + sh_ss[6] + sh_ss[7];
        if (bs != 0.0f) atomicAdd(&g_norm[t], bs);
    }
}

// ============================================================================
// Update kernel: clipped SGD (+ big-degree mean-pool branch)
// ============================================================================
__global__ void k_update(const float* __restrict__ rep_, float* __restrict__ out_, int t) {
    const int i = blockIdx.x * blockDim.x + threadIdx.x;  // over NN*32 float4s
    if (i >= NN * (DD / 4)) return;
    float S = g_norm[t];
    float coef = fminf(1.0f, 2.0f / (sqrtf(S) + 1e-6f));
    int node = i >> 5;
    float4 res;
    if (g_deg[node] > BIGDEG) {
        res = reinterpret_cast<const float4*>(g_mean)[i];
    } else {
        float4 r = reinterpret_cast<const float4*>(rep_)[i];
        float4 g = reinterpret_cast<const float4*>(g_grad)[i];
        res = make_float4(r.x - coef * g.x, r.y - coef * g.y,
                          r.z - coef * g.z, r.w - coef * g.w);
    }
    reinterpret_cast<float4*>(out_)[i] = res;
}

// ============================================================================
// Host: JAX key derivation (split(key(1),20) -> per-iter randint subkeys)
// ============================================================================
static void derive_keys(uint32_t* k1x, uint32_t* k1y, uint32_t* k2x, uint32_t* k2y) {
    uint32_t kt0[NITER], kt1[NITER];
    uint32_t dummy0, dummy1;
    (void)dummy0; (void)dummy1;
    for (int t = 0; t < NITER; t++)
        tf2x32(0u, 1u, 0u, (uint32_t)t, kt0[t], kt1[t]);
    for (int t = 0; t < NITER; t++) {
        tf2x32(kt0[t], kt1[t], 0u, 0u, k1x[t], k1y[t]);
        tf2x32(kt0[t], kt1[t], 0u, 1u, k2x[t], k2y[t]);
    }
}

// ============================================================================
// Entry point
// ============================================================================
extern "C" void kernel_launch(void* const* d_in, const int* in_sizes, int n_in,
                              void* d_out, int out_size) {
    const float* repre = (const float*)d_in[0];
    const int*   src   = (const int*)d_in[1];
    const int*   dst   = (const int*)d_in[2];
    float*       out   = (float*)d_out;

    float *repA, *repB;
    cudaGetSymbolAddress((void**)&repA, g_repA);
    cudaGetSymbolAddress((void**)&repB, g_repB);

    uint32_t k1x[NITER], k1y[NITER], k2x[NITER], k2y[NITER];
    derive_keys(k1x, k1y, k2x, k2y);

    const int TB = 256;
    // ---- build phase (once per launch, amortized over 20 iterations) ----
    k_zero<<<(NN + TB - 1) / TB, TB>>>();
    k_hist<<<(EE + TB - 1) / TB, TB>>>(dst);
    k_scan<<<1, 1024>>>();
    k_scatter<<<(EE + TB - 1) / TB, TB>>>(src, dst);
    k_copy<<<(NN * (DD / 4) + TB - 1) / TB, TB>>>((const float4*)repre);

    // ---- 20 iterations, ping-pong buffers, final iter writes d_out ----
    float* cur = repA;
    for (int t = 0; t < NITER; t++) {
        k_meangrad<<<NN / 8, 256>>>(cur, t, k1x[t], k1y[t], k2x[t], k2y[t]);
        float* nxt = (t == NITER - 1) ? out : ((cur == repA) ? repB : repA);
        k_update<<<(NN * (DD / 4) + TB - 1) / TB, TB>>>(cur, nxt, t);
        cur = nxt;
    }
}